// round 2
// baseline (speedup 1.0000x reference)
#include <cuda_runtime.h>
#include <cuda_bf16.h>
#include <cstdint>

// Problem constants
#define BB 32
#define CC 128
#define NN 16384
#define KK 64
#define TN 64          // n-tile width
#define SPLITS 16      // n-splits per batch
#define TILES ((NN / SPLITS) / TN)   // 16 tiles per block
#define LDX 66         // padded leading dim for x tile  [128][66]
#define LDL 66         // padded leading dim for logits  [64][66]
#define EPSV 1e-12f

// Scratch (allocation-free rule: __device__ globals)
__device__ float g_agg[BB * KK * CC];   // 1 MB
__device__ float g_asum[BB * KK];

// ---------------------------------------------------------------------------
__global__ void zero_scratch() {
    int i = blockIdx.x * blockDim.x + threadIdx.x;
    const int tot = BB * KK * CC + BB * KK;
    for (; i < tot; i += gridDim.x * blockDim.x) {
        if (i < BB * KK * CC) g_agg[i] = 0.0f;
        else g_asum[i - BB * KK * CC] = 0.0f;
    }
}

// ---------------------------------------------------------------------------
// Fused: logits GEMM -> relu+softmax(K) -> aggregation GEMM (+ a row-sums)
// grid (SPLITS, BB), 256 threads
__global__ __launch_bounds__(256, 2) void netvlad_main(
    const float* __restrict__ x,
    const float* __restrict__ conv_w,
    const float* __restrict__ conv_b)
{
    extern __shared__ float smem[];
    float* sW = smem;                       // [64][128]   8192
    float* sB = sW + KK * CC;               // [64]          64
    float* sX = sB + KK;                    // [128][66]   8448
    float* sL = sX + CC * LDX;              // [64][66]    4224

    const int b     = blockIdx.y;
    const int split = blockIdx.x;
    const int t     = threadIdx.x;

    // Load conv_w / conv_b once
    for (int i = t; i < KK * CC; i += 256) sW[i] = conv_w[i];
    if (t < KK) sB[t] = conv_b[t];

    // Phase-1 mapping: 4k x 4n per thread
    const int ng1 = t & 15;        // n = ng1*4 + j
    const int kq1 = t >> 4;        // k = kq1*4 + i
    // Softmax mapping: 4 sub-threads per column
    const int col = t >> 2;
    const int sub = t & 3;
    // Phase-3 mapping: 4k x 8c per thread (c strided by 16 -> conflict-free)
    const int cg  = t & 15;        // c = cg + 16*j
    const int kq3 = t >> 4;        // k = kq3*4 + i

    float vacc[4][8];
    #pragma unroll
    for (int i = 0; i < 4; i++)
        #pragma unroll
        for (int j = 0; j < 8; j++) vacc[i][j] = 0.0f;
    float sacc[4] = {0.f, 0.f, 0.f, 0.f};

    const int n_base0 = split * (NN / SPLITS);
    const float* xb = x + (size_t)b * CC * NN;

    __syncthreads();   // sW/sB ready

    for (int tile = 0; tile < TILES; tile++) {
        const int n0 = n_base0 + tile * TN;

        // ---- stage x tile: 128 rows x 64 floats, coalesced float4 ----
        {
            const int row_in = t >> 4;        // 0..15
            const int j4     = (t & 15) * 4;  // 0..60
            #pragma unroll
            for (int p = 0; p < 8; p++) {
                int c = p * 16 + row_in;
                float4 v = *(const float4*)(xb + (size_t)c * NN + n0 + j4);
                float* d = &sX[c * LDX + j4];
                d[0] = v.x; d[1] = v.y; d[2] = v.z; d[3] = v.w;
            }
        }
        __syncthreads();

        // ---- phase 1: logits[k][n] = sum_c w[k][c] * x[c][n] ----
        {
            float acc[4][4];
            #pragma unroll
            for (int i = 0; i < 4; i++)
                #pragma unroll
                for (int j = 0; j < 4; j++) acc[i][j] = 0.0f;

            const int n1 = ng1 * 4;
            #pragma unroll 4
            for (int c = 0; c < CC; c += 2) {
                float2 x0a = *(const float2*)&sX[c * LDX + n1];
                float2 x0b = *(const float2*)&sX[c * LDX + n1 + 2];
                float2 x1a = *(const float2*)&sX[(c + 1) * LDX + n1];
                float2 x1b = *(const float2*)&sX[(c + 1) * LDX + n1 + 2];
                #pragma unroll
                for (int i = 0; i < 4; i++) {
                    float2 w = *(const float2*)&sW[(kq1 * 4 + i) * CC + c];
                    acc[i][0] = fmaf(w.y, x1a.x, fmaf(w.x, x0a.x, acc[i][0]));
                    acc[i][1] = fmaf(w.y, x1a.y, fmaf(w.x, x0a.y, acc[i][1]));
                    acc[i][2] = fmaf(w.y, x1b.x, fmaf(w.x, x0b.x, acc[i][2]));
                    acc[i][3] = fmaf(w.y, x1b.y, fmaf(w.x, x0b.y, acc[i][3]));
                }
            }
            #pragma unroll
            for (int i = 0; i < 4; i++) {
                float bias = sB[kq1 * 4 + i];
                #pragma unroll
                for (int j = 0; j < 4; j++)
                    sL[(kq1 * 4 + i) * LDL + n1 + j] = acc[i][j] + bias;
            }
        }
        __syncthreads();

        // ---- phase 2: softmax(relu(logits)) over k, per column n ----
        {
            float e[16];
            float m = 0.0f;   // relu => max >= 0
            #pragma unroll
            for (int i = 0; i < 16; i++) {
                float v = sL[(sub + 4 * i) * LDL + col];
                v = fmaxf(v, 0.0f);
                e[i] = v;
                m = fmaxf(m, v);
            }
            m = fmaxf(m, __shfl_xor_sync(0xffffffffu, m, 1));
            m = fmaxf(m, __shfl_xor_sync(0xffffffffu, m, 2));
            float s = 0.0f;
            #pragma unroll
            for (int i = 0; i < 16; i++) {
                e[i] = __expf(e[i] - m);
                s += e[i];
            }
            s += __shfl_xor_sync(0xffffffffu, s, 1);
            s += __shfl_xor_sync(0xffffffffu, s, 2);
            float inv = 1.0f / s;
            #pragma unroll
            for (int i = 0; i < 16; i++)
                sL[(sub + 4 * i) * LDL + col] = e[i] * inv;
        }
        __syncthreads();

        // ---- phase 3: vacc[k][c] += sum_n a[k][n]*x[c][n]; sacc[k] += a ----
        {
            #pragma unroll 2
            for (int n = 0; n < TN; n += 2) {
                float2 av[4];
                #pragma unroll
                for (int i = 0; i < 4; i++)
                    av[i] = *(const float2*)&sL[(kq3 * 4 + i) * LDL + n];
                float2 xv[8];
                #pragma unroll
                for (int j = 0; j < 8; j++)
                    xv[j] = *(const float2*)&sX[(cg + 16 * j) * LDX + n];
                #pragma unroll
                for (int i = 0; i < 4; i++)
                    #pragma unroll
                    for (int j = 0; j < 8; j++) {
                        vacc[i][j] = fmaf(av[i].x, xv[j].x, vacc[i][j]);
                        vacc[i][j] = fmaf(av[i].y, xv[j].y, vacc[i][j]);
                    }
                if (cg == 0) {
                    #pragma unroll
                    for (int i = 0; i < 4; i++)
                        sacc[i] += av[i].x + av[i].y;
                }
            }
        }
        __syncthreads();
    }

    // ---- accumulate partials to global ----
    float* agg = g_agg + (size_t)b * KK * CC;
    #pragma unroll
    for (int i = 0; i < 4; i++) {
        int k = kq3 * 4 + i;
        #pragma unroll
        for (int j = 0; j < 8; j++) {
            int c = cg + 16 * j;
            atomicAdd(&agg[k * CC + c], vacc[i][j]);
        }
    }
    if (cg == 0) {
        #pragma unroll
        for (int i = 0; i < 4; i++)
            atomicAdd(&g_asum[b * KK + kq3 * 4 + i], sacc[i]);
    }
}

// ---------------------------------------------------------------------------
// Finalize: residual vs centroids, intra-norm (over C), global norm (over K*C)
// grid (BB), 256 threads (8 warps, each warp: 8 rows)
__global__ __launch_bounds__(256) void netvlad_finalize(
    const float* __restrict__ centroids,
    float* __restrict__ out)
{
    __shared__ float sred[8];
    const int b = blockIdx.x;
    const int t = threadIdx.x;
    const int lane = t & 31;
    const int w = t >> 5;

    const float* agg = g_agg + (size_t)b * KK * CC;
    const float* as  = g_asum + b * KK;

    float v[8][4];
    float gss = 0.0f;

    #pragma unroll
    for (int r = 0; r < 8; r++) {
        const int k = w * 8 + r;
        const float s = as[k];
        const int c4 = lane * 4;
        float4 a = *(const float4*)&agg[k * CC + c4];
        float4 cn = *(const float4*)&centroids[k * CC + c4];
        v[r][0] = a.x - s * cn.x;
        v[r][1] = a.y - s * cn.y;
        v[r][2] = a.z - s * cn.z;
        v[r][3] = a.w - s * cn.w;
        float ss = v[r][0]*v[r][0] + v[r][1]*v[r][1] + v[r][2]*v[r][2] + v[r][3]*v[r][3];
        #pragma unroll
        for (int off = 16; off > 0; off >>= 1)
            ss += __shfl_xor_sync(0xffffffffu, ss, off);
        float scale = 1.0f / fmaxf(sqrtf(ss), EPSV);
        #pragma unroll
        for (int j = 0; j < 4; j++) {
            v[r][j] *= scale;
            gss += v[r][j] * v[r][j];
        }
    }

    #pragma unroll
    for (int off = 16; off > 0; off >>= 1)
        gss += __shfl_xor_sync(0xffffffffu, gss, off);
    if (lane == 0) sred[w] = gss;
    __syncthreads();
    float tot = 0.0f;
    #pragma unroll
    for (int i = 0; i < 8; i++) tot += sred[i];
    float gscale = 1.0f / fmaxf(sqrtf(tot), EPSV);

    #pragma unroll
    for (int r = 0; r < 8; r++) {
        const int k = w * 8 + r;
        float4 o;
        o.x = v[r][0] * gscale;
        o.y = v[r][1] * gscale;
        o.z = v[r][2] * gscale;
        o.w = v[r][3] * gscale;
        *(float4*)&out[(size_t)b * KK * CC + k * CC + lane * 4] = o;
    }
}

// ---------------------------------------------------------------------------
extern "C" void kernel_launch(void* const* d_in, const int* in_sizes, int n_in,
                              void* d_out, int out_size)
{
    const float* x         = (const float*)d_in[0];
    const float* conv_w    = (const float*)d_in[1];
    const float* conv_b    = (const float*)d_in[2];
    const float* centroids = (const float*)d_in[3];
    float* out = (float*)d_out;

    const int smem_bytes = (KK * CC + KK + CC * LDX + KK * LDL) * (int)sizeof(float);
    static bool attr_set = false;
    if (!attr_set) {
        cudaFuncSetAttribute(netvlad_main,
                             cudaFuncAttributeMaxDynamicSharedMemorySize,
                             smem_bytes);
        attr_set = true;
    }

    zero_scratch<<<264, 1024>>>();
    dim3 grid(SPLITS, BB);
    netvlad_main<<<grid, 256, smem_bytes>>>(x, conv_w, conv_b);
    netvlad_finalize<<<BB, 256>>>(centroids, out);
}